// round 5
// baseline (speedup 1.0000x reference)
#include <cuda_runtime.h>

// SSD post-processing: decode + per-class greedy NMS.
//   loc_data  [8, 3000, 4]  f32
//   conf_data [8, 3000, 21] f32
//   priors    [3000, 4]     f32
//   out       [8, 21, 200, 5] f32  (score, x1, y1, x2, y2), zero-padded
//
// 80 CTAs x 512 threads; each CTA = 2 independent 256-thread halves, one
// (batch, class) problem per half, synced with named barriers (bar.sync h+1).
// One wave on 148 SMs, 16 warps/SM.
//
// Per half:
//   Sort: bitonic on 4096 u64 (score,~idx) keys; strides >=16 in smem
//         (pair-expanded), strides <=8 register-fused (16 keys/thread,
//         XOR-swizzled banks).
//   NMS (candidate-driven: kept(j) <=> IoU vs every earlier kept <= 0.45):
//     tiles of 256 (1 cand/thread).
//     Phase A (parallel): each thread decodes its candidate and tests it vs
//       the committed accepted list with early-out; per-warp ballot -> smem.
//     Phase B (warp 0, barrier-free): alive bits in registers (bit m of lane
//       l = candidate m*32+l); next = ffs + redux.min + ballot; broadcast via
//       shfl; 8 register IoUs/lane to self-suppress. 2 barriers per tile.

#define NP    3000
#define NPAD  4096
#define NC    21
#define TOPK  200
#define NTH   256                 // threads per half
#define NTT   512                 // threads per CTA
#define EPT   (NPAD / NTH)        // 16 keys/thread in the fused sort
#define SW(i) ((i) ^ (((i) >> 4) & 15))

typedef unsigned long long ull;

// dynamic smem layout (bytes)
#define OFF_KEYS   0                     // 2 * 4096 * 8  = 65536
#define OFF_SBOX   65536                 // 2 * 256 * 16  = 8192
#define OFF_SSC    (OFF_SBOX + 8192)     // 2 * 256 * 4   = 2048
#define OFF_ABOX   (OFF_SSC + 2048)      // 2 * 200 * 16  = 6400
#define OFF_ALV    (OFF_ABOX + 6400)     // 2 * 8 * 4     = 64
#define OFF_CNT    (OFF_ALV + 64)        // 2 * 4         = 8
#define SMEM_BYTES (OFF_CNT + 8)

#define BARH() asm volatile("bar.sync %0, %1;" :: "r"(h + 1), "r"(256) : "memory")

__device__ __forceinline__ void cexch(ull& a, ull& b, bool desc) {
    if (desc ? (a < b) : (a > b)) { ull t = a; a = b; b = t; }
}

// reference-exact IoU (no FMA contraction)
__device__ __forceinline__ float iou_rn(float ax1, float ay1, float ax2, float ay2, float aa,
                                        float bx1, float by1, float bx2, float by2, float ba)
{
    float ltx = fmaxf(ax1, bx1);
    float lty = fmaxf(ay1, by1);
    float rbx = fminf(ax2, bx2);
    float rby = fminf(ay2, by2);
    float wx  = fmaxf(__fsub_rn(rbx, ltx), 0.0f);
    float wy  = fmaxf(__fsub_rn(rby, lty), 0.0f);
    float inter = __fmul_rn(wx, wy);
    float uni   = __fsub_rn(__fadd_rn(aa, ba), inter);
    return __fdiv_rn(inter, fmaxf(uni, 1e-12f));
}

__global__ __launch_bounds__(NTT, 1) void ssd_post_kernel(
    const float* __restrict__ loc,
    const float* __restrict__ conf,
    const float* __restrict__ priors,
    float* __restrict__ out)
{
    extern __shared__ unsigned char smem_raw[];

    const int tid  = threadIdx.x;
    const int h    = tid >> 8;        // half: 0 or 1
    const int tidh = tid & 255;
    const int lane = tid & 31;
    const int wixh = tidh >> 5;

    const int g    = blockIdx.x;      // 0..79
    const int b    = g / 10;
    const int pair = g % 10;
    const int c    = 1 + pair * 2 + h;   // classes 1..20

    ull*    keys  = (ull*)   (smem_raw + OFF_KEYS + h * (NPAD * 8));
    float4* sbox  = (float4*)(smem_raw + OFF_SBOX + h * (NTH * 16));
    float*  ssc   = (float*) (smem_raw + OFF_SSC  + h * (NTH * 4));
    float4* abox  = (float4*)(smem_raw + OFF_ABOX + h * (TOPK * 16));
    int*    salv  = (int*)   (smem_raw + OFF_ALV) + h * 8;
    int*    scnt  = (int*)   (smem_raw + OFF_CNT) + h;

    // zero my half's output slice (harness poisons d_out)
    float* outp = out + (size_t)(b * NC + c) * (TOPK * 5);
    for (int k = tidh; k < TOPK * 5; k += NTH) outp[k] = 0.0f;
    if (pair == 0) {  // also zero the background (class 0) slice of image b
        float* o0 = out + (size_t)(b * NC) * (TOPK * 5);
        for (int k = tid; k < TOPK * 5; k += NTT) o0[k] = 0.0f;
    }
    if (tidh == 0) *scnt = 0;

    // ---- build sort keys: (sortable(score) << 32) | ~idx  (stable desc) ----
    const float* confb = conf + (size_t)b * NP * NC + c;
    #pragma unroll
    for (int w = 0; w < EPT; ++w) {
        int p = tidh + w * NTH;
        ull key = 0ULL;                               // padding: below everything
        if (p < NP) {
            float s = confb[(size_t)p * NC];
            if (!(s > 0.01f)) s = __int_as_float(0xff800000);  // -inf suffix
            unsigned u = __float_as_uint(s);
            u = (u & 0x80000000u) ? ~u : (u | 0x80000000u);
            key = ((ull)u << 32) | (unsigned)(~p);
        }
        keys[SW(p)] = key;
    }
    BARH();

    // ---- bitonic sort, descending ----
    // fused register-local stages k = 2..16 (all strides < 16)
    {
        const int base = tidh * EPT;
        ull r[EPT];
        #pragma unroll
        for (int m = 0; m < EPT; ++m) r[m] = keys[SW(base + m)];
        #pragma unroll
        for (int k = 2; k <= 16; k <<= 1) {
            #pragma unroll
            for (int j = k >> 1; j >= 1; j >>= 1) {
                #pragma unroll
                for (int m = 0; m < EPT; ++m)
                    if (!(m & j))
                        cexch(r[m], r[m | j], ((base + m) & k) == 0);
            }
        }
        #pragma unroll
        for (int m = 0; m < EPT; ++m) keys[SW(base + m)] = r[m];
    }
    BARH();

    for (int k = 32; k <= NPAD; k <<= 1) {
        // smem substages: strides >= 16, pair-expanded (all threads active)
        for (int j = k >> 1; j >= 16; j >>= 1) {
            #pragma unroll
            for (int w = 0; w < NPAD / (2 * NTH); ++w) {
                int p   = tidh + w * NTH;
                int i   = ((p & ~(j - 1)) << 1) | (p & (j - 1));
                int ixj = i | j;
                ull a  = keys[SW(i)];
                ull bb = keys[SW(ixj)];
                if (((i & k) == 0) ? (a < bb) : (a > bb)) {
                    keys[SW(i)] = bb; keys[SW(ixj)] = a;
                }
            }
            BARH();
        }
        // register-local tail: strides 8,4,2,1 (uniform direction per thread)
        {
            const int  base = tidh * EPT;
            const bool desc = ((base & k) == 0);
            ull r[EPT];
            #pragma unroll
            for (int m = 0; m < EPT; ++m) r[m] = keys[SW(base + m)];
            #pragma unroll
            for (int j = 8; j >= 1; j >>= 1) {
                #pragma unroll
                for (int m = 0; m < EPT; ++m)
                    if (!(m & j)) cexch(r[m], r[m | j], desc);
            }
            #pragma unroll
            for (int m = 0; m < EPT; ++m) keys[SW(base + m)] = r[m];
        }
        BARH();
    }

    // ---- tiled candidate-driven NMS ----
    const float* locb = loc + (size_t)b * NP * 4;

    for (int tb = 0; tb < NP; tb += NTH) {
        const int cnt0 = *scnt;          // committed before last barrier
        if (cnt0 >= TOPK) break;         // uniform within the half

        const int j = tb + tidh;         // rank of my candidate (< 3072 < NPAD)
        ull  key     = keys[SW(j)];
        bool myAlive = (key >> 63) != 0; // valid <=> score > 0.01

        // decode my candidate (exact reference op order) + hand to resolver
        float mx1 = 0.f, my1 = 0.f, mx2 = 0.f, my2 = 0.f, mar = 0.f;
        if (myAlive) {
            int idx  = (int)(~(unsigned)key);
            float ms = __uint_as_float((unsigned)(key >> 32) & 0x7FFFFFFFu);
            float4 l  = *(const float4*)(locb + (size_t)idx * 4);
            float4 pr = *(const float4*)(priors + (size_t)idx * 4);
            float cx = __fadd_rn(pr.x, __fmul_rn(__fmul_rn(l.x, 0.1f), pr.z));
            float cy = __fadd_rn(pr.y, __fmul_rn(__fmul_rn(l.y, 0.1f), pr.w));
            float w  = __fmul_rn(pr.z, expf(__fmul_rn(l.z, 0.2f)));
            float hh = __fmul_rn(pr.w, expf(__fmul_rn(l.w, 0.2f)));
            mx1 = __fsub_rn(cx, __fmul_rn(0.5f, w));
            my1 = __fsub_rn(cy, __fmul_rn(0.5f, hh));
            mx2 = __fadd_rn(mx1, w);
            my2 = __fadd_rn(my1, hh);
            mar = __fmul_rn(__fsub_rn(mx2, mx1), __fsub_rn(my2, my1));
            sbox[tidh] = make_float4(mx1, my1, mx2, my2);
            ssc[tidh]  = ms;
        }

        // Phase A: test vs committed accepted list, early-out on overlap
        if (myAlive) {
            for (int q = 0; q < cnt0; ++q) {
                float4 ab = abox[q];
                float aa  = __fmul_rn(__fsub_rn(ab.z, ab.x), __fsub_rn(ab.w, ab.y));
                if (iou_rn(mx1, my1, mx2, my2, mar, ab.x, ab.y, ab.z, ab.w, aa) > 0.45f) {
                    myAlive = false; break;
                }
            }
        }
        unsigned wm = __ballot_sync(0xffffffffu, myAlive);
        if (lane == 0) salv[wixh] = (int)wm;
        BARH();

        // Phase B: warp 0 resolves the whole tile, barrier-free
        if (wixh == 0) {
            // alive bits: bit m of lane l <=> candidate m*32+l alive
            unsigned alive8 = 0;
            #pragma unroll
            for (int m = 0; m < 8; ++m)
                alive8 |= (((unsigned)salv[m] >> lane) & 1u) << m;

            // my 8 candidates' boxes + areas
            float4 cb[8]; float ca[8];
            #pragma unroll
            for (int m = 0; m < 8; ++m) cb[m] = sbox[m * 32 + lane];
            #pragma unroll
            for (int m = 0; m < 8; ++m)
                ca[m] = __fmul_rn(__fsub_rn(cb[m].z, cb[m].x), __fsub_rn(cb[m].w, cb[m].y));

            int cnt = cnt0;
            while (cnt < TOPK) {
                unsigned mlow  = alive8 ? (unsigned)(__ffs(alive8) - 1) : 99u;
                unsigned mstar = __reduce_min_sync(0xffffffffu, mlow);
                if (mstar == 99u) break;                 // tile exhausted
                unsigned sel = __ballot_sync(0xffffffffu, mlow == mstar);
                int L = __ffs(sel) - 1;                  // accepted = mstar*32 + L

                // uniform-index select of my cb[mstar], then broadcast lane L's
                float vx1 = cb[0].x, vy1 = cb[0].y, vx2 = cb[0].z, vy2 = cb[0].w;
                #pragma unroll
                for (int m = 1; m < 8; ++m)
                    if (mstar == (unsigned)m) { vx1 = cb[m].x; vy1 = cb[m].y; vx2 = cb[m].z; vy2 = cb[m].w; }
                float cx1 = __shfl_sync(0xffffffffu, vx1, L);
                float cy1 = __shfl_sync(0xffffffffu, vy1, L);
                float cx2 = __shfl_sync(0xffffffffu, vx2, L);
                float cy2 = __shfl_sync(0xffffffffu, vy2, L);
                float car = __fmul_rn(__fsub_rn(cx2, cx1), __fsub_rn(cy2, cy1));

                if (lane == L) {
                    abox[cnt] = make_float4(cx1, cy1, cx2, cy2);
                    float* o = outp + cnt * 5;
                    o[0] = ssc[mstar * 32 + lane];
                    o[1] = cx1; o[2] = cy1; o[3] = cx2; o[4] = cy2;
                }

                // suppress my candidates vs the new accept (self iou=1 clears it)
                unsigned kill = 0;
                #pragma unroll
                for (int m = 0; m < 8; ++m) {
                    float ii = iou_rn(cb[m].x, cb[m].y, cb[m].z, cb[m].w, ca[m],
                                      cx1, cy1, cx2, cy2, car);
                    if (ii > 0.45f) kill |= (1u << m);
                }
                alive8 &= ~kill;
                cnt++;
            }
            if (lane == 0) *scnt = cnt;
        }
        BARH();   // publish abox/scnt to the next tile's Phase A
    }
}

extern "C" void kernel_launch(void* const* d_in, const int* in_sizes, int n_in,
                              void* d_out, int out_size)
{
    const float* loc = nullptr;
    const float* conf = nullptr;
    const float* priors = nullptr;
    for (int i = 0; i < n_in; i++) {
        if (in_sizes[i] == 8 * NP * 4)       loc    = (const float*)d_in[i];
        else if (in_sizes[i] == 8 * NP * NC) conf   = (const float*)d_in[i];
        else if (in_sizes[i] == NP * 4)      priors = (const float*)d_in[i];
    }
    float* out = (float*)d_out;

    cudaFuncSetAttribute(ssd_post_kernel,
                         cudaFuncAttributeMaxDynamicSharedMemorySize, SMEM_BYTES);

    ssd_post_kernel<<<80, NTT, SMEM_BYTES>>>(loc, conf, priors, out);
}